// round 1
// baseline (speedup 1.0000x reference)
#include <cuda_runtime.h>

#define NX 4096
#define NY 4096

static __device__ __constant__ float c_DT     = 5e-4f;
static __device__ __constant__ float c_INV2DX = 500.0f;   // 1/(2*1e-3)
static __device__ __constant__ float c_INV2DY = 500.0f;

__global__ __launch_bounds__(256) void fdtd_step_kernel(
    const float* __restrict__ Ez,
    const float* __restrict__ Hx,
    const float* __restrict__ Hy,
    const float* __restrict__ eps,
    const float* __restrict__ mu,
    const float* __restrict__ sig,
    float* __restrict__ out_ez,
    float* __restrict__ out_hx,
    float* __restrict__ out_hy)
{
    const int j = blockIdx.x * blockDim.x + threadIdx.x;   // contiguous dim
    const int i = blockIdx.y * blockDim.y + threadIdx.y;
    if (i >= NX || j >= NY) return;

    const long idx = (long)i * NY + j;

    const float DT     = c_DT;
    const float INV2DX = c_INV2DX;
    const float INV2DY = c_INV2DY;

    const bool int_i = (i >= 1) && (i < NX - 1);
    const bool int_j = (j >= 1) && (j < NY - 1);
    const bool interior = int_i && int_j;

    const float ez_c = __ldg(&Ez[idx]);
    const float hx_c = __ldg(&Hx[idx]);
    const float hy_c = __ldg(&Hy[idx]);
    const float mu_c = __ldg(&mu[idx]);

    // --- H updates at the center cell ---
    // derivatives are nonzero only when BOTH indices are interior
    float ddy_c = 0.0f, ddx_c = 0.0f;
    if (interior) {
        ddy_c = (__ldg(&Ez[idx + 1])  - __ldg(&Ez[idx - 1]))  * INV2DY;
        ddx_c = (__ldg(&Ez[idx + NY]) - __ldg(&Ez[idx - NY])) * INV2DX;
    }
    const float hxn_c = hx_c - DT * (ddy_c / mu_c);
    const float hyn_c = hy_c + DT * (ddx_c / mu_c);

    out_hx[idx] = hxn_c;
    out_hy[idx] = hyn_c;

    // --- Ez update ---
    const float e = __ldg(&eps[idx]);
    const float s = __ldg(&sig[idx]);
    const float half_sdt_over_e = s * (DT * 0.5f) / e;
    const float A_plus  = 1.0f + half_sdt_over_e;
    const float A_minus = 1.0f - half_sdt_over_e;
    const float inv_Ap  = 1.0f / A_plus;

    float ez_new = (A_minus * inv_Ap) * ez_c;

    if (interior) {
        // hy_new at (i+1, j): ddx there needs i+1 <= NX-2  (j already interior)
        float hyn_p, hyn_m, hxn_p, hxn_m;
        {
            const long idp = idx + NY;
            float d = 0.0f;
            if (i + 1 < NX - 1)
                d = (__ldg(&Ez[idp + NY]) - __ldg(&Ez[idp - NY])) * INV2DX;
            hyn_p = __ldg(&Hy[idp]) + DT * (d / __ldg(&mu[idp]));
        }
        // hy_new at (i-1, j): needs i-1 >= 1
        {
            const long idm = idx - NY;
            float d = 0.0f;
            if (i - 1 >= 1)
                d = (__ldg(&Ez[idm + NY]) - __ldg(&Ez[idm - NY])) * INV2DX;
            hyn_m = __ldg(&Hy[idm]) + DT * (d / __ldg(&mu[idm]));
        }
        // hx_new at (i, j+1): ddy there needs j+1 <= NY-2  (i already interior)
        {
            const long idp = idx + 1;
            float d = 0.0f;
            if (j + 1 < NY - 1)
                d = (__ldg(&Ez[idp + 1]) - __ldg(&Ez[idp - 1])) * INV2DY;
            hxn_p = __ldg(&Hx[idp]) - DT * (d / __ldg(&mu[idp]));
        }
        // hx_new at (i, j-1): needs j-1 >= 1
        {
            const long idm = idx - 1;
            float d = 0.0f;
            if (j - 1 >= 1)
                d = (__ldg(&Ez[idm + 1]) - __ldg(&Ez[idm - 1])) * INV2DY;
            hxn_m = __ldg(&Hx[idm]) - DT * (d / __ldg(&mu[idm]));
        }

        const float curl = (hyn_p - hyn_m) * INV2DX - (hxn_p - hxn_m) * INV2DY;
        ez_new += (DT * inv_Ap / e) * curl;
    }

    out_ez[idx] = ez_new;
}

extern "C" void kernel_launch(void* const* d_in, const int* in_sizes, int n_in,
                              void* d_out, int out_size)
{
    const float* Ez  = (const float*)d_in[0];
    const float* Hx  = (const float*)d_in[1];
    const float* Hy  = (const float*)d_in[2];
    const float* eps = (const float*)d_in[3];
    const float* mu  = (const float*)d_in[4];
    const float* sig = (const float*)d_in[5];

    float* out = (float*)d_out;
    const long N = (long)NX * NY;
    float* out_ez = out;
    float* out_hx = out + N;
    float* out_hy = out + 2 * N;

    dim3 block(128, 2);
    dim3 grid(NY / 128, NX / 2);
    fdtd_step_kernel<<<grid, block>>>(Ez, Hx, Hy, eps, mu, sig,
                                      out_ez, out_hx, out_hy);
}

// round 3
// speedup vs baseline: 1.3587x; 1.3587x over previous
#include <cuda_runtime.h>

#define NX 4096
#define NY 4096
#define DT   5e-4f
#define INV2 500.0f   // 1/(2*dx) = 1/(2*dy)

__device__ __forceinline__ float4 ld4(const float* __restrict__ p) {
    return __ldg(reinterpret_cast<const float4*>(p));
}

__device__ __forceinline__ float frcp(float x) {
    float r;
    asm("rcp.approx.f32 %0, %1;" : "=f"(r) : "f"(x));
    return r;
}

__device__ __forceinline__ float lane(const float4& v, int l) {
    return (l == 0) ? v.x : (l == 1) ? v.y : (l == 2) ? v.z : v.w;
}
__device__ __forceinline__ void setlane(float4& v, int l, float f) {
    if      (l == 0) v.x = f;
    else if (l == 1) v.y = f;
    else if (l == 2) v.z = f;
    else             v.w = f;
}

__global__ __launch_bounds__(256) void fdtd_v4_kernel(
    const float* __restrict__ Ez,
    const float* __restrict__ Hx,
    const float* __restrict__ Hy,
    const float* __restrict__ eps,
    const float* __restrict__ mu,
    const float* __restrict__ sig,
    float* __restrict__ oez,
    float* __restrict__ ohx,
    float* __restrict__ ohy)
{
    const int jv = blockIdx.x * blockDim.x + threadIdx.x;   // vector index along j
    const int i  = blockIdx.y * blockDim.y + threadIdx.y;
    const int j0 = jv << 2;
    const long base = (long)i * NY + j0;

    const bool int_i   = (i >= 1) && (i <= NX - 2);
    const bool has_im1 = (i >= 1);
    const bool has_ip1 = (i <= NX - 2);
    const bool has_im2 = (i >= 2);        // ddx at row i-1 valid
    const bool has_ip2 = (i <= NX - 3);   // ddx at row i+1 valid

    const float4 z4   = make_float4(0.f, 0.f, 0.f, 0.f);
    const float4 one4 = make_float4(1.f, 1.f, 1.f, 1.f);

    // ---- row i: Ez cols j0-2..j0+5 ----
    const float4 ez_c = ld4(Ez + base);
    const float4 ez_l = (j0 > 0)      ? ld4(Ez + base - 4) : z4;
    const float4 ez_r = (j0 + 4 < NY) ? ld4(Ez + base + 4) : z4;
    const float ezr[8] = {ez_l.z, ez_l.w, ez_c.x, ez_c.y,
                          ez_c.z, ez_c.w, ez_r.x, ez_r.y};

    // ---- row i: Hx cols j0-1..j0+4 ----
    const float4 hx_c = ld4(Hx + base);
    const float4 hx_l = (j0 > 0)      ? ld4(Hx + base - 4) : z4;
    const float4 hx_r = (j0 + 4 < NY) ? ld4(Hx + base + 4) : z4;
    const float hxr[6] = {hx_l.w, hx_c.x, hx_c.y, hx_c.z, hx_c.w, hx_r.x};

    // ---- row i: mu cols j0-1..j0+4 (reciprocals) ----
    const float4 mu_c = ld4(mu + base);
    const float4 mu_l = (j0 > 0)      ? ld4(mu + base - 4) : one4;
    const float4 mu_r = (j0 + 4 < NY) ? ld4(mu + base + 4) : one4;
    const float rmur[6] = {frcp(mu_l.w), frcp(mu_c.x), frcp(mu_c.y),
                           frcp(mu_c.z), frcp(mu_c.w), frcp(mu_r.x)};

    // ---- neighbor rows ----
    const float4 ez_m1 = has_im1 ? ld4(Ez + base - NY)     : z4;
    const float4 ez_p1 = has_ip1 ? ld4(Ez + base + NY)     : z4;
    const float4 ez_m2 = has_im2 ? ld4(Ez + base - 2 * NY) : z4;
    const float4 ez_p2 = has_ip2 ? ld4(Ez + base + 2 * NY) : z4;

    const float4 hy_c  = ld4(Hy + base);
    const float4 hy_m1 = has_im1 ? ld4(Hy + base - NY) : z4;
    const float4 hy_p1 = has_ip1 ? ld4(Hy + base + NY) : z4;

    const float4 mu_m1v = has_im1 ? ld4(mu + base - NY) : one4;
    const float4 mu_p1v = has_ip1 ? ld4(mu + base + NY) : one4;
    const float4 rmu_m1 = make_float4(frcp(mu_m1v.x), frcp(mu_m1v.y),
                                      frcp(mu_m1v.z), frcp(mu_m1v.w));
    const float4 rmu_p1 = make_float4(frcp(mu_p1v.x), frcp(mu_p1v.y),
                                      frcp(mu_p1v.z), frcp(mu_p1v.w));

    const float4 ep4 = ld4(eps + base);
    const float4 sg4 = ld4(sig + base);

    float4 out_ez4, out_hx4, out_hy4;

#pragma unroll
    for (int l = 0; l < 4; ++l) {
        const int  j     = j0 + l;
        const bool int_j = (j >= 1) && (j <= NY - 2);
        const bool interior = int_i && int_j;

        const float ezc = ezr[l + 2];
        const float rmu = rmur[l + 1];

        // center H update
        float ddy = interior ? (ezr[l + 3] - ezr[l + 1]) * INV2 : 0.f;
        float ddx = interior ? (lane(ez_p1, l) - lane(ez_m1, l)) * INV2 : 0.f;
        const float hxn = hxr[l + 1] - DT * ddy * rmu;
        const float hyn = lane(hy_c, l) + DT * ddx * rmu;
        setlane(out_hx4, l, hxn);
        setlane(out_hy4, l, hyn);

        // Ez update
        const float e   = lane(ep4, l);
        const float s   = lane(sg4, l);
        const float re  = frcp(e);
        const float h   = s * (0.5f * DT) * re;
        const float rAp = frcp(1.0f + h);
        float ezn = (1.0f - h) * rAp * ezc;

        if (interior) {
            // hy_new at (i+1, j)
            const float dp   = has_ip2 ? (lane(ez_p2, l) - ezc) * INV2 : 0.f;
            const float hynp = lane(hy_p1, l) + DT * dp * lane(rmu_p1, l);
            // hy_new at (i-1, j)
            const float dm   = has_im2 ? (ezc - lane(ez_m2, l)) * INV2 : 0.f;
            const float hynm = lane(hy_m1, l) + DT * dm * lane(rmu_m1, l);
            // hx_new at (i, j+1)
            const float djp  = (j + 1 <= NY - 2) ? (ezr[l + 4] - ezc) * INV2 : 0.f;
            const float hxnp = hxr[l + 2] - DT * djp * rmur[l + 2];
            // hx_new at (i, j-1)
            const float djm  = (j - 1 >= 1) ? (ezc - ezr[l]) * INV2 : 0.f;
            const float hxnm = hxr[l] - DT * djm * rmur[l];

            const float curl = (hynp - hynm) * INV2 - (hxnp - hxnm) * INV2;
            ezn += (DT * rAp * re) * curl;
        }
        setlane(out_ez4, l, ezn);
    }

    *reinterpret_cast<float4*>(oez + base) = out_ez4;
    *reinterpret_cast<float4*>(ohx + base) = out_hx4;
    *reinterpret_cast<float4*>(ohy + base) = out_hy4;
}

extern "C" void kernel_launch(void* const* d_in, const int* in_sizes, int n_in,
                              void* d_out, int out_size)
{
    const float* Ez  = (const float*)d_in[0];
    const float* Hx  = (const float*)d_in[1];
    const float* Hy  = (const float*)d_in[2];
    const float* eps = (const float*)d_in[3];
    const float* mu  = (const float*)d_in[4];
    const float* sig = (const float*)d_in[5];

    float* out = (float*)d_out;
    const long N = (long)NX * NY;

    dim3 block(128, 2);                      // 128 vec4-threads cover 512 cols
    dim3 grid((NY / 4) / 128, NX / 2);       // (8, 2048)
    fdtd_v4_kernel<<<grid, block>>>(Ez, Hx, Hy, eps, mu, sig,
                                    out, out + N, out + 2 * N);
}

// round 4
// speedup vs baseline: 1.4635x; 1.0772x over previous
#include <cuda_runtime.h>

#define NX 4096
#define NY 4096
#define DT    5e-4f
#define INV2  500.0f   // 1/(2*dx) = 1/(2*dy)

__device__ __forceinline__ float4 ld4(const float* __restrict__ p) {
    return __ldg(reinterpret_cast<const float4*>(p));
}

__device__ __forceinline__ float frcp(float x) {
    float r;
    asm("rcp.approx.f32 %0, %1;" : "=f"(r) : "f"(x));
    return r;
}

__device__ __forceinline__ float lane(const float4& v, int l) {
    return (l == 0) ? v.x : (l == 1) ? v.y : (l == 2) ? v.z : v.w;
}
__device__ __forceinline__ void setlane(float4& v, int l, float f) {
    if      (l == 0) v.x = f;
    else if (l == 1) v.y = f;
    else if (l == 2) v.z = f;
    else             v.w = f;
}

__global__ __launch_bounds__(256, 4) void fdtd_v4_kernel(
    const float* __restrict__ Ez,
    const float* __restrict__ Hx,
    const float* __restrict__ Hy,
    const float* __restrict__ eps,
    const float* __restrict__ mu,
    const float* __restrict__ sig,
    float* __restrict__ oez,
    float* __restrict__ ohx,
    float* __restrict__ ohy)
{
    const int jv = blockIdx.x * blockDim.x + threadIdx.x;   // vector index along j
    const int i  = blockIdx.y * blockDim.y + threadIdx.y;
    const int j0 = jv << 2;
    const long base = (long)i * NY + j0;

    const bool  int_i   = (i >= 1) && (i <= NX - 2);
    const float m_int_i = int_i ? 1.0f : 0.0f;
    const bool  has_im1 = (i >= 1);
    const bool  has_ip1 = (i <= NX - 2);
    const float m_im2   = (i >= 2)      ? 1.0f : 0.0f;   // ddx valid at row i-1
    const float m_ip2   = (i <= NX - 3) ? 1.0f : 0.0f;   // ddx valid at row i+1

    const bool jlo = (j0 > 0);
    const bool jhi = (j0 + 4 < NY);

    const float4 z4   = make_float4(0.f, 0.f, 0.f, 0.f);
    const float4 one4 = make_float4(1.f, 1.f, 1.f, 1.f);

    // ---- row i: Ez cols j0-2..j0+5 ----
    const float4 ez_c = ld4(Ez + base);
    const float4 ez_l = jlo ? ld4(Ez + base - 4) : z4;
    const float4 ez_r = jhi ? ld4(Ez + base + 4) : z4;
    const float ezr[8] = {ez_l.z, ez_l.w, ez_c.x, ez_c.y,
                          ez_c.z, ez_c.w, ez_r.x, ez_r.y};

    // ---- row i: Hx cols j0-1..j0+4 ----
    const float4 hx_c = ld4(Hx + base);
    const float4 hx_l = jlo ? ld4(Hx + base - 4) : z4;
    const float4 hx_r = jhi ? ld4(Hx + base + 4) : z4;
    const float hxr[6] = {hx_l.w, hx_c.x, hx_c.y, hx_c.z, hx_c.w, hx_r.x};

    // ---- row i: mu cols j0-1..j0+4 (reciprocals) ----
    const float4 mu_c = ld4(mu + base);
    const float4 mu_l = jlo ? ld4(mu + base - 4) : one4;
    const float4 mu_r = jhi ? ld4(mu + base + 4) : one4;
    const float rmur[6] = {frcp(mu_l.w), frcp(mu_c.x), frcp(mu_c.y),
                           frcp(mu_c.z), frcp(mu_c.w), frcp(mu_r.x)};

    // ---- neighbor rows ----
    const float4 ez_m1 = has_im1 ? ld4(Ez + base - NY)     : z4;
    const float4 ez_p1 = has_ip1 ? ld4(Ez + base + NY)     : z4;
    const float4 ez_m2 = (i >= 2)      ? ld4(Ez + base - 2 * NY) : z4;
    const float4 ez_p2 = (i <= NX - 3) ? ld4(Ez + base + 2 * NY) : z4;

    const float4 hy_c  = ld4(Hy + base);
    const float4 hy_m1 = has_im1 ? ld4(Hy + base - NY) : z4;
    const float4 hy_p1 = has_ip1 ? ld4(Hy + base + NY) : z4;

    const float4 mu_m1v = has_im1 ? ld4(mu + base - NY) : one4;
    const float4 mu_p1v = has_ip1 ? ld4(mu + base + NY) : one4;
    const float4 rmu_m1 = make_float4(frcp(mu_m1v.x), frcp(mu_m1v.y),
                                      frcp(mu_m1v.z), frcp(mu_m1v.w));
    const float4 rmu_p1 = make_float4(frcp(mu_p1v.x), frcp(mu_p1v.y),
                                      frcp(mu_p1v.z), frcp(mu_p1v.w));

    const float4 ep4 = ld4(eps + base);
    const float4 sg4 = ld4(sig + base);

    float4 out_ez4, out_hx4, out_hy4;

    const float DTI = DT * INV2;   // fused DT * (1/2dx)

#pragma unroll
    for (int l = 0; l < 4; ++l) {
        const int   j     = j0 + l;
        const float m_j   = ((j >= 1) && (j <= NY - 2)) ? 1.0f : 0.0f;
        const float m_int = m_int_i * m_j;

        const float ezc = ezr[l + 2];
        const float rmu = rmur[l + 1];

        // center H update (masked derivatives, branchless)
        const float ddy = (ezr[l + 3] - ezr[l + 1]) * m_int;
        const float ddx = (lane(ez_p1, l) - lane(ez_m1, l)) * m_int;
        const float hxn = hxr[l + 1] - DTI * ddy * rmu;
        const float hyn = lane(hy_c, l) + DTI * ddx * rmu;
        setlane(out_hx4, l, hxn);
        setlane(out_hy4, l, hyn);

        // Ez coefficients via single reciprocal:
        //   a = (eps - c)/(eps + c),  b = DT/(eps + c),  c = 0.5*DT*sig
        const float e    = lane(ep4, l);
        const float c    = (0.5f * DT) * lane(sg4, l);
        const float rden = frcp(e + c);
        float ezn = (e - c) * rden * ezc;

        // neighbor H-new values (masked so boundary contributions vanish)
        const float dp   = (lane(ez_p2, l) - ezc) * m_ip2;
        const float hynp = lane(hy_p1, l) + DTI * dp * lane(rmu_p1, l);
        const float dm   = (ezc - lane(ez_m2, l)) * m_im2;
        const float hynm = lane(hy_m1, l) + DTI * dm * lane(rmu_m1, l);

        const float mjp  = (j + 1 <= NY - 2) ? 1.0f : 0.0f;
        const float djp  = (ezr[l + 4] - ezc) * mjp;
        const float hxnp = hxr[l + 2] - DTI * djp * rmur[l + 2];
        const float mjm  = (j >= 2) ? 1.0f : 0.0f;
        const float djm  = (ezc - ezr[l]) * mjm;
        const float hxnm = hxr[l] - DTI * djm * rmur[l];

        const float curl = (hynp - hynm - hxnp + hxnm) * INV2;
        ezn += (DT * rden) * curl * m_int;

        setlane(out_ez4, l, ezn);
    }

    *reinterpret_cast<float4*>(oez + base) = out_ez4;
    *reinterpret_cast<float4*>(ohx + base) = out_hx4;
    *reinterpret_cast<float4*>(ohy + base) = out_hy4;
}

extern "C" void kernel_launch(void* const* d_in, const int* in_sizes, int n_in,
                              void* d_out, int out_size)
{
    const float* Ez  = (const float*)d_in[0];
    const float* Hx  = (const float*)d_in[1];
    const float* Hy  = (const float*)d_in[2];
    const float* eps = (const float*)d_in[3];
    const float* mu  = (const float*)d_in[4];
    const float* sig = (const float*)d_in[5];

    float* out = (float*)d_out;
    const long N = (long)NX * NY;

    dim3 block(128, 2);                      // 128 vec4-threads cover 512 cols
    dim3 grid((NY / 4) / 128, NX / 2);       // (8, 2048)
    fdtd_v4_kernel<<<grid, block>>>(Ez, Hx, Hy, eps, mu, sig,
                                    out, out + N, out + 2 * N);
}